// round 6
// baseline (speedup 1.0000x reference)
#include <cuda_runtime.h>
#include <cuda_bf16.h>
#include <math.h>

#define H_DIM 2
#define L_LAYERS 4
#define R_RELS 16
#define B_BASES 8
#define N_NODES 1000000
#define E_EDGES 16000000
#define EPT 8
#define ETHREADS (E_EDGES / EPT)   // 2,000,000

// ---- device scratch (allocation-free rule) --------------------------------
__device__ float2 g_x[N_NODES];
__device__ float2 g_h[N_NODES];
__device__ float2 g_skip[N_NODES];
__device__ int2   g_pk[E_EDGES];        // {src | type<<20, dst}  (128 MB)
__device__ float4 g_W[L_LAYERS * R_RELS];
__device__ float  g_acc;

// ---------------------------------------------------------------------------
__global__ void compute_weights_kernel(const float* __restrict__ V,
                                       const float* __restrict__ comp) {
    int tid = threadIdx.x;
    if (tid >= L_LAYERS * R_RELS) return;
    int l = tid / R_RELS, r = tid % R_RELS;
    float w0 = 0.f, w1 = 0.f, w2 = 0.f, w3 = 0.f;
    #pragma unroll
    for (int b = 0; b < B_BASES; b++) {
        float c = comp[(l * R_RELS + r) * B_BASES + b];
        const float* v = V + ((l * B_BASES + b) * 4);
        w0 += c * v[0]; w1 += c * v[1]; w2 += c * v[2]; w3 += c * v[3];
    }
    g_W[tid] = make_float4(w0, w1, w2, w3);   // (w00,w01,w10,w11)
}

__global__ void zero_kernel() {
    int i = blockIdx.x * blockDim.x + threadIdx.x;
    if (i == 0) g_acc = 0.f;
    if (i < N_NODES) g_h[i] = make_float2(0.f, 0.f);
}

// ---------------------------------------------------------------------------
// Layer 0: gathers from `features` directly, packs edges for layers 1-3.
__global__ void __launch_bounds__(256) layer0_kernel(
        const float2* __restrict__ feat,
        const int4* __restrict__ src4,
        const int4* __restrict__ dst4,
        const int4* __restrict__ type4,
        const float4* __restrict__ norm4) {
    __shared__ float4 sW[R_RELS];
    if (threadIdx.x < R_RELS) sW[threadIdx.x] = g_W[threadIdx.x];
    __syncthreads();

    int i = blockIdx.x * blockDim.x + threadIdx.x;
    if (i >= ETHREADS) return;
    int q = i * 2;

    int4   s0 = src4[q],  s1 = src4[q + 1];
    int4   d0 = dst4[q],  d1 = dst4[q + 1];
    int4   t0 = type4[q], t1 = type4[q + 1];
    float4 n0 = norm4[q], n1 = norm4[q + 1];

    int   ss[EPT] = {s0.x, s0.y, s0.z, s0.w, s1.x, s1.y, s1.z, s1.w};
    int   dd[EPT] = {d0.x, d0.y, d0.z, d0.w, d1.x, d1.y, d1.z, d1.w};
    int   tt[EPT] = {t0.x, t0.y, t0.z, t0.w, t1.x, t1.y, t1.z, t1.w};
    float nn[EPT] = {n0.x, n0.y, n0.z, n0.w, n1.x, n1.y, n1.z, n1.w};

    // packed payload for layers 1-3 (sequential 64B per thread)
    int4* pk4 = (int4*)g_pk;        // one int4 = 2 packed edges
    #pragma unroll
    for (int k = 0; k < EPT / 2; k++) {
        pk4[i * 4 + k] = make_int4(ss[2 * k]     | (tt[2 * k] << 20),
                                   dd[2 * k],
                                   ss[2 * k + 1] | (tt[2 * k + 1] << 20),
                                   dd[2 * k + 1]);
    }

    float2 xs[EPT];
    #pragma unroll
    for (int k = 0; k < EPT; k++) xs[k] = __ldg(&feat[ss[k]]);

    #pragma unroll
    for (int k = 0; k < EPT; k++) {
        float4 w = sW[tt[k]];
        float mx = (xs[k].x * w.x + xs[k].y * w.z) * nn[k];
        float my = (xs[k].x * w.y + xs[k].y * w.w) * nn[k];
        atomicAdd(&g_h[dd[k]], make_float2(mx, my));
    }
}

// ---------------------------------------------------------------------------
// Layers 1-3: stream packed int2 + fp32 norm (12 B/edge).
__global__ void __launch_bounds__(256) layer_kernel(
        int l, const float4* __restrict__ norm4) {
    __shared__ float4 sW[R_RELS];
    if (threadIdx.x < R_RELS) sW[threadIdx.x] = g_W[l * R_RELS + threadIdx.x];
    __syncthreads();

    int i = blockIdx.x * blockDim.x + threadIdx.x;
    if (i >= ETHREADS) return;

    const int4* pk4 = (const int4*)g_pk;
    int4 p0 = pk4[i * 4 + 0];
    int4 p1 = pk4[i * 4 + 1];
    int4 p2 = pk4[i * 4 + 2];
    int4 p3 = pk4[i * 4 + 3];
    float4 n0 = norm4[i * 2], n1 = norm4[i * 2 + 1];

    int st[EPT] = {p0.x, p0.z, p1.x, p1.z, p2.x, p2.z, p3.x, p3.z};
    int dd[EPT] = {p0.y, p0.w, p1.y, p1.w, p2.y, p2.w, p3.y, p3.w};
    float nn[EPT] = {n0.x, n0.y, n0.z, n0.w, n1.x, n1.y, n1.z, n1.w};

    float2 xs[EPT];
    #pragma unroll
    for (int k = 0; k < EPT; k++) xs[k] = __ldg(&g_x[st[k] & 0xFFFFF]);

    #pragma unroll
    for (int k = 0; k < EPT; k++) {
        float4 w = sW[(st[k] >> 20) & 0xF];
        float mx = (xs[k].x * w.x + xs[k].y * w.z) * nn[k];
        float my = (xs[k].x * w.y + xs[k].y * w.w) * nn[k];
        atomicAdd(&g_h[dd[k]], make_float2(mx, my));
    }
}

// ---------------------------------------------------------------------------
// Epilogue variants. All re-zero h for the next layer.
// relu only (after layers 0 and 2):  x = relu(h + b)
__global__ void epi_relu_kernel(int l, const float* __restrict__ bias) {
    int i = blockIdx.x * blockDim.x + threadIdx.x;
    if (i >= N_NODES) return;
    float2 h = g_h[i];
    float hx = fmaxf(h.x + __ldg(&bias[2 * l]), 0.f);
    float hy = fmaxf(h.y + __ldg(&bias[2 * l + 1]), 0.f);
    g_x[i] = make_float2(hx, hy);
    g_h[i] = make_float2(0.f, 0.f);
}

// after layer 1: x = relu(h + b1) + features; skip = x
__global__ void epi_skip_kernel(const float* __restrict__ bias,
                                const float2* __restrict__ feat) {
    int i = blockIdx.x * blockDim.x + threadIdx.x;
    if (i >= N_NODES) return;
    float2 h = g_h[i];
    float2 f = feat[i];
    float hx = fmaxf(h.x + __ldg(&bias[2]), 0.f) + f.x;
    float hy = fmaxf(h.y + __ldg(&bias[3]), 0.f) + f.y;
    float2 v = make_float2(hx, hy);
    g_x[i] = v;
    g_skip[i] = v;
    g_h[i] = make_float2(0.f, 0.f);
}

// ---------------------------------------------------------------------------
// Fused final epilogue + dot:  logit += w . ((h3 + b3) + skip)
__global__ void dot_kernel(const float4* __restrict__ w4,
                           const float* __restrict__ bias) {
    float b3x = __ldg(&bias[6]);
    float b3y = __ldg(&bias[7]);
    const int npairs = N_NODES / 2;     // 2 nodes per float4 of w
    float sum = 0.f;
    for (int i = blockIdx.x * blockDim.x + threadIdx.x; i < npairs;
         i += gridDim.x * blockDim.x) {
        float4 w = w4[i];
        float2 ha = g_h[2 * i], hb = g_h[2 * i + 1];
        float2 sa = g_skip[2 * i], sb = g_skip[2 * i + 1];
        sum += w.x * (ha.x + b3x + sa.x) + w.y * (ha.y + b3y + sa.y)
             + w.z * (hb.x + b3x + sb.x) + w.w * (hb.y + b3y + sb.y);
    }
    #pragma unroll
    for (int off = 16; off > 0; off >>= 1)
        sum += __shfl_down_sync(0xFFFFFFFFu, sum, off);
    __shared__ float ws[8];
    int lane = threadIdx.x & 31, wid = threadIdx.x >> 5;
    if (lane == 0) ws[wid] = sum;
    __syncthreads();
    if (wid == 0) {
        sum = (lane < (blockDim.x >> 5)) ? ws[lane] : 0.f;
        #pragma unroll
        for (int off = 4; off > 0; off >>= 1)
            sum += __shfl_down_sync(0xFFFFFFFFu, sum, off);
        if (lane == 0) atomicAdd(&g_acc, sum);
    }
}

__global__ void finalize_kernel(const float* __restrict__ b_mlp,
                                float* __restrict__ out) {
    float logit = g_acc + b_mlp[0];
    out[0] = 1.f / (1.f + expf(-logit));
}

// ---------------------------------------------------------------------------
extern "C" void kernel_launch(void* const* d_in, const int* in_sizes, int n_in,
                              void* d_out, int out_size) {
    const float* features  = (const float*)d_in[0];
    const float* norm      = (const float*)d_in[1];
    const float* V         = (const float*)d_in[2];
    const float* comp      = (const float*)d_in[3];
    const float* bias      = (const float*)d_in[4];
    const float* w_mlp     = (const float*)d_in[5];
    const float* b_mlp     = (const float*)d_in[6];
    const int*   edge_src  = (const int*)d_in[7];
    const int*   edge_dst  = (const int*)d_in[8];
    const int*   edge_type = (const int*)d_in[9];
    float*       out       = (float*)d_out;

    const int TB = 256;
    const int node_blocks = (N_NODES + TB - 1) / TB;
    const int edge_blocks = (ETHREADS + TB - 1) / TB;

    compute_weights_kernel<<<1, 64>>>(V, comp);
    zero_kernel<<<node_blocks, TB>>>();

    layer0_kernel<<<edge_blocks, TB>>>((const float2*)features,
                                       (const int4*)edge_src,
                                       (const int4*)edge_dst,
                                       (const int4*)edge_type,
                                       (const float4*)norm);
    epi_relu_kernel<<<node_blocks, TB>>>(0, bias);

    layer_kernel<<<edge_blocks, TB>>>(1, (const float4*)norm);
    epi_skip_kernel<<<node_blocks, TB>>>(bias, (const float2*)features);

    layer_kernel<<<edge_blocks, TB>>>(2, (const float4*)norm);
    epi_relu_kernel<<<node_blocks, TB>>>(2, bias);

    layer_kernel<<<edge_blocks, TB>>>(3, (const float4*)norm);

    dot_kernel<<<1024, TB>>>((const float4*)w_mlp, bias);
    finalize_kernel<<<1, 1>>>(b_mlp, out);
}

// round 7
// speedup vs baseline: 1.1096x; 1.1096x over previous
#include <cuda_runtime.h>
#include <cuda_bf16.h>
#include <math.h>

#define H_DIM 2
#define L_LAYERS 4
#define R_RELS 16
#define B_BASES 8
#define N_NODES 1000000
#define E_EDGES 16000000

// ---- device scratch (allocation-free rule) --------------------------------
__device__ float2 g_x[N_NODES];
__device__ float2 g_h[N_NODES];
__device__ float2 g_skip[N_NODES];
__device__ float4 g_W[L_LAYERS * R_RELS];   // (w00,w01,w10,w11) per [l][r]
__device__ float  g_acc;

// ---------------------------------------------------------------------------
__global__ void compute_weights_kernel(const float* __restrict__ V,
                                       const float* __restrict__ comp) {
    int tid = threadIdx.x;
    if (tid >= L_LAYERS * R_RELS) return;
    int l = tid / R_RELS, r = tid % R_RELS;
    float w0 = 0.f, w1 = 0.f, w2 = 0.f, w3 = 0.f;
    #pragma unroll
    for (int b = 0; b < B_BASES; b++) {
        float c = comp[(l * R_RELS + r) * B_BASES + b];
        const float* v = V + ((l * B_BASES + b) * 4);
        w0 += c * v[0]; w1 += c * v[1]; w2 += c * v[2]; w3 += c * v[3];
    }
    g_W[tid] = make_float4(w0, w1, w2, w3);
}

// h = 0; acc = 0
__global__ void zero_kernel() {
    int i = blockIdx.x * blockDim.x + threadIdx.x;
    if (i == 0) g_acc = 0.f;
    if (i < N_NODES) g_h[i] = make_float2(0.f, 0.f);
}

// ---------------------------------------------------------------------------
// Edge kernel (R1-proven shape): 4 edges/thread, vectorized streams,
// gather xin[src], float2 RED scatter to h[dst].
__global__ void __launch_bounds__(256) edge_kernel(
        const float2* __restrict__ xin,
        const int4* __restrict__ src4,
        const int4* __restrict__ dst4,
        const int4* __restrict__ type4,
        const float4* __restrict__ norm4,
        int l) {
    __shared__ float4 sW[R_RELS];
    if (threadIdx.x < R_RELS) sW[threadIdx.x] = g_W[l * R_RELS + threadIdx.x];
    __syncthreads();

    int i = blockIdx.x * blockDim.x + threadIdx.x;
    if (i >= E_EDGES / 4) return;

    int4   s  = src4[i];
    int4   d  = dst4[i];
    int4   t  = type4[i];
    float4 nm = norm4[i];

    int   ss[4] = {s.x, s.y, s.z, s.w};
    int   dd[4] = {d.x, d.y, d.z, d.w};
    int   tt[4] = {t.x, t.y, t.z, t.w};
    float nn[4] = {nm.x, nm.y, nm.z, nm.w};

    #pragma unroll
    for (int k = 0; k < 4; k++) {
        float2 xs = __ldg(&xin[ss[k]]);
        float4 w = sW[tt[k]];
        float mx = (xs.x * w.x + xs.y * w.z) * nn[k];
        float my = (xs.x * w.y + xs.y * w.w) * nn[k];
        atomicAdd(&g_h[dd[k]], make_float2(mx, my));
    }
}

// ---------------------------------------------------------------------------
// Epilogues: consume h, produce x, re-zero h in the same pass.
// After layers 0 and 2:  x = relu(h + b)
__global__ void epi_relu_kernel(int l, const float* __restrict__ bias) {
    int i = blockIdx.x * blockDim.x + threadIdx.x;
    if (i >= N_NODES) return;
    float2 h = g_h[i];
    g_x[i] = make_float2(fmaxf(h.x + __ldg(&bias[2 * l]), 0.f),
                         fmaxf(h.y + __ldg(&bias[2 * l + 1]), 0.f));
    g_h[i] = make_float2(0.f, 0.f);
}

// After layer 1:  x = relu(h + b1) + features;  skip = x
__global__ void epi_skip_kernel(const float* __restrict__ bias,
                                const float2* __restrict__ feat) {
    int i = blockIdx.x * blockDim.x + threadIdx.x;
    if (i >= N_NODES) return;
    float2 h = g_h[i];
    float2 f = feat[i];
    float2 v = make_float2(fmaxf(h.x + __ldg(&bias[2]), 0.f) + f.x,
                           fmaxf(h.y + __ldg(&bias[3]), 0.f) + f.y);
    g_x[i] = v;
    g_skip[i] = v;
    g_h[i] = make_float2(0.f, 0.f);
}

// ---------------------------------------------------------------------------
// Fused final epilogue + dot:  acc += w . ((h3 + b3) + skip)
__global__ void dot_kernel(const float4* __restrict__ w4,
                           const float* __restrict__ bias) {
    float b3x = __ldg(&bias[6]);
    float b3y = __ldg(&bias[7]);
    const int npairs = N_NODES / 2;   // one float4 of w covers 2 nodes
    float sum = 0.f;
    for (int i = blockIdx.x * blockDim.x + threadIdx.x; i < npairs;
         i += gridDim.x * blockDim.x) {
        float4 w = w4[i];
        float2 ha = g_h[2 * i],    hb = g_h[2 * i + 1];
        float2 sa = g_skip[2 * i], sb = g_skip[2 * i + 1];
        sum += w.x * (ha.x + b3x + sa.x) + w.y * (ha.y + b3y + sa.y)
             + w.z * (hb.x + b3x + sb.x) + w.w * (hb.y + b3y + sb.y);
    }
    #pragma unroll
    for (int off = 16; off > 0; off >>= 1)
        sum += __shfl_down_sync(0xFFFFFFFFu, sum, off);
    __shared__ float ws[8];
    int lane = threadIdx.x & 31, wid = threadIdx.x >> 5;
    if (lane == 0) ws[wid] = sum;
    __syncthreads();
    if (wid == 0) {
        sum = (lane < (blockDim.x >> 5)) ? ws[lane] : 0.f;
        #pragma unroll
        for (int off = 4; off > 0; off >>= 1)
            sum += __shfl_down_sync(0xFFFFFFFFu, sum, off);
        if (lane == 0) atomicAdd(&g_acc, sum);
    }
}

__global__ void finalize_kernel(const float* __restrict__ b_mlp,
                                float* __restrict__ out) {
    float logit = g_acc + b_mlp[0];
    out[0] = 1.f / (1.f + expf(-logit));
}

// ---------------------------------------------------------------------------
extern "C" void kernel_launch(void* const* d_in, const int* in_sizes, int n_in,
                              void* d_out, int out_size) {
    const float* features  = (const float*)d_in[0];
    const float* norm      = (const float*)d_in[1];
    const float* V         = (const float*)d_in[2];
    const float* comp      = (const float*)d_in[3];
    const float* bias      = (const float*)d_in[4];
    const float* w_mlp     = (const float*)d_in[5];
    const float* b_mlp     = (const float*)d_in[6];
    const int*   edge_src  = (const int*)d_in[7];
    const int*   edge_dst  = (const int*)d_in[8];
    const int*   edge_type = (const int*)d_in[9];
    float*       out       = (float*)d_out;

    const int TB = 256;
    const int node_blocks = (N_NODES + TB - 1) / TB;
    const int edge_blocks = (E_EDGES / 4 + TB - 1) / TB;   // 15625

    const int4*   s4 = (const int4*)edge_src;
    const int4*   d4 = (const int4*)edge_dst;
    const int4*   t4 = (const int4*)edge_type;
    const float4* n4 = (const float4*)norm;

    void* px = nullptr;
    cudaGetSymbolAddress(&px, g_x);
    const float2* fx = (const float2*)px;

    compute_weights_kernel<<<1, 64>>>(V, comp);
    zero_kernel<<<node_blocks, TB>>>();

    // L0: gather features directly
    edge_kernel<<<edge_blocks, TB>>>((const float2*)features, s4, d4, t4, n4, 0);
    epi_relu_kernel<<<node_blocks, TB>>>(0, bias);

    edge_kernel<<<edge_blocks, TB>>>(fx, s4, d4, t4, n4, 1);
    epi_skip_kernel<<<node_blocks, TB>>>(bias, (const float2*)features);

    edge_kernel<<<edge_blocks, TB>>>(fx, s4, d4, t4, n4, 2);
    epi_relu_kernel<<<node_blocks, TB>>>(2, bias);

    edge_kernel<<<edge_blocks, TB>>>(fx, s4, d4, t4, n4, 3);

    dot_kernel<<<1024, TB>>>((const float4*)w_mlp, bias);
    finalize_kernel<<<1, 1>>>(b_mlp, out);
}